// round 7
// baseline (speedup 1.0000x reference)
#include <cuda_runtime.h>
#include <cuda_bf16.h>
#include <math.h>
#include <stdint.h>

// ----- problem constants (B=16, T=512, D=512) -----
constexpr int Bn = 16;
constexpr int Tn = 512;
constexpr int Dn = 512;
constexpr int BT = Bn * Tn;            // 8192
constexpr int TOTPAD = 8320;           // 130*64 max bank rows (padded)
constexpr int NTL_MAX = 130;           // worst-case 64-wide n tiles
constexpr int TILE = 64;               // M and N tile
constexpr int KSTG = 64;               // K elems per smem stage
constexpr int NKC = Dn / KSTG;         // 8 K-stages
constexpr int STRIDE = 144;            // bytes per smem row (128 data + 16 pad)
constexpr int STG_BYTES = 128 * STRIDE;// 18432 (64 A rows + 64 B rows)
constexpr int STAGES = 3;
constexpr int DYN_BYTES = STAGES * STG_BYTES;   // 55296 -> 4 CTAs/SM
constexpr int NWORKERS = 592;          // 4 per SM

// ----- device scratch (no allocations allowed) -----
__device__ __nv_bfloat16 g_hidb[2 * BT * Dn];    // [dir][row][512]
__device__ __nv_bfloat16 g_bankb[TOTPAD * Dn];   // zero-padded bank, bf16
__device__ int   g_src[TOTPAD];
__device__ int   g_rowhid[BT];
__device__ int   g_rowbatch[BT];
__device__ int   g_L[Bn];
__device__ float g_invL[Bn];
__device__ int   g_S, g_total, g_mt, g_ntl, g_nitems, g_work;
__device__ float g_pm[2 * NTL_MAX * BT];
__device__ float g_ps[2 * NTL_MAX * BT];
__device__ float g_lse[2 * BT];
__device__ float g_diag[2 * BT];

// ----- helpers -----
__device__ __forceinline__ uint32_t smem_u32(const void* p) {
    uint32_t a;
    asm("{ .reg .u64 t; cvta.to.shared.u64 t, %1; cvt.u32.u64 %0, t; }" : "=r"(a) : "l"(p));
    return a;
}
__device__ __forceinline__ void cp16(uint32_t dst, const void* src) {
    asm volatile("cp.async.cg.shared.global [%0], [%1], 16;" :: "r"(dst), "l"(src) : "memory");
}
__device__ __forceinline__ void cp_commit() {
    asm volatile("cp.async.commit_group;" ::: "memory");
}
__device__ __forceinline__ void cp_wait1() {
    asm volatile("cp.async.wait_group 1;" ::: "memory");
}
__device__ __forceinline__ void ldsm_x4(uint32_t* r, uint32_t a) {
    asm volatile("ldmatrix.sync.aligned.m8n8.x4.shared.b16 {%0,%1,%2,%3}, [%4];"
                 : "=r"(r[0]), "=r"(r[1]), "=r"(r[2]), "=r"(r[3]) : "r"(a));
}
__device__ __forceinline__ void ldsm_x4t(uint32_t& r0, uint32_t& r1, uint32_t& r2, uint32_t& r3, uint32_t a) {
    asm volatile("ldmatrix.sync.aligned.m8n8.x4.trans.shared.b16 {%0,%1,%2,%3}, [%4];"
                 : "=r"(r0), "=r"(r1), "=r"(r2), "=r"(r3) : "r"(a));
}
__device__ __forceinline__ void mma16816(float* c, const uint32_t* a, uint32_t b0, uint32_t b1) {
    asm volatile("mma.sync.aligned.m16n8k16.row.col.f32.bf16.bf16.f32 "
                 "{%0,%1,%2,%3}, {%4,%5,%6,%7}, {%8,%9}, {%0,%1,%2,%3};"
                 : "+f"(c[0]), "+f"(c[1]), "+f"(c[2]), "+f"(c[3])
                 : "r"(a[0]), "r"(a[1]), "r"(a[2]), "r"(a[3]), "r"(b0), "r"(b1));
}
__device__ __forceinline__ uint32_t f2bf2(float lo, float hi) {
    uint32_t r;
    asm("cvt.rn.bf16x2.f32 %0, %1, %2;" : "=r"(r) : "f"(hi), "f"(lo));
    return r;
}

// ------------------------------------------------------------------
// 1) layout setup (single block)
// ------------------------------------------------------------------
__global__ void setup_kernel(const int* __restrict__ seq_lens) {
    __shared__ int sL[Bn], sCum[Bn + 1], sStart[Bn];
    int tid = threadIdx.x;
    if (tid == 0) {
        int c = 0;
        for (int i = 0; i < Bn; i++) {
            sL[i] = seq_lens[i];
            sCum[i] = c;
            sStart[i] = 2 * i + c;
            c += sL[i];
        }
        sCum[Bn] = c;
        g_S = c;
        g_total = c + 2 * Bn;
        g_mt = (c + TILE - 1) / TILE;
        g_ntl = (g_total + TILE - 1) / TILE;
        g_nitems = g_mt * g_ntl * 2;
        g_work = 0;
    }
    __syncthreads();
    int S = sCum[Bn];
    int total = S + 2 * Bn;
    if (tid < Bn) { g_invL[tid] = 1.0f / (float)sL[tid]; g_L[tid] = sL[tid]; }

    for (int r = tid; r < TOTPAD; r += blockDim.x) {
        int src = -1;
        if (r < total) {
            for (int i = 0; i < Bn; i++) {
                int s0 = sStart[i];
                if (r >= s0 && r < s0 + sL[i] + 2) {
                    if (r > s0 && r < s0 + sL[i] + 1) src = i * Tn + (r - s0 - 1);
                    break;
                }
            }
        }
        g_src[r] = src;
    }
    for (int r = tid; r < BT; r += blockDim.x) {
        if (r < S) {
            int b = 0;
            for (int i = 0; i < Bn; i++)
                if (r >= sCum[i] && r < sCum[i + 1]) { b = i; break; }
            int t = r - sCum[b];
            g_rowhid[r] = b * Tn + t;
            g_rowbatch[r] = b;
        } else {
            g_rowhid[r] = 0; g_rowbatch[r] = 0;
        }
    }
}

// ------------------------------------------------------------------
// 2) fused conversion: hidden -> per-dir bf16, feats -> bf16 bank
// ------------------------------------------------------------------
__global__ void cvt_kernel(const float* __restrict__ hidden,
                           const float* __restrict__ feats) {
    int blk = blockIdx.x;
    int tid = threadIdx.x;
    if (blk < BT) {
        float4 v = reinterpret_cast<const float4*>(hidden)[blk * 256 + tid];
        int dir = tid >= 128;
        int col = tid * 4 - dir * 512;
        uint2 o = make_uint2(f2bf2(v.x, v.y), f2bf2(v.z, v.w));
        *reinterpret_cast<uint2*>(&g_hidb[((size_t)dir * BT + blk) * Dn + col]) = o;
    } else if (tid < 128) {
        int row = blk - BT;
        int src = g_src[row];
        float4 v = make_float4(0.f, 0.f, 0.f, 0.f);
        if (src >= 0) v = reinterpret_cast<const float4*>(feats)[src * 128 + tid];
        uint2 o = make_uint2(f2bf2(v.x, v.y), f2bf2(v.z, v.w));
        *reinterpret_cast<uint2*>(&g_bankb[(size_t)row * Dn + tid * 4]) = o;
    }
}

// ------------------------------------------------------------------
// 3) exact fp32 diagonal logits
// ------------------------------------------------------------------
__global__ void diag_kernel(const float* __restrict__ hidden,
                            const float* __restrict__ feats) {
    int r = blockIdx.x * 8 + (threadIdx.x >> 5);
    if (r >= g_S) return;
    int dir = blockIdx.y;
    int lane = threadIdx.x & 31;
    int hrow = g_rowhid[r];
    int b = hrow >> 9, t = hrow & 511;
    bool ok = dir == 0 ? (t + 1 < g_L[b]) : (t > 0);
    float sum = 0.f;
    if (ok) {
        int frow = hrow + (dir == 0 ? 1 : -1);
        const float4* h = reinterpret_cast<const float4*>(hidden + (size_t)hrow * 1024 + dir * Dn);
        const float4* x = reinterpret_cast<const float4*>(feats + (size_t)frow * Dn);
#pragma unroll
        for (int j = 0; j < 4; j++) {
            float4 a = h[lane + j * 32];
            float4 c = x[lane + j * 32];
            sum += a.x * c.x + a.y * c.y + a.z * c.z + a.w * c.w;
        }
#pragma unroll
        for (int o = 16; o >= 1; o >>= 1) sum += __shfl_xor_sync(0xffffffffu, sum, o);
    }
    if (lane == 0) g_diag[dir * BT + r] = sum;
}

// ------------------------------------------------------------------
// 4) persistent mma.sync GEMM + per-tile LSE partials
//    592 CTAs x 128 threads (4/SM, independent barrier domains)
//    tile 64x64, 2x2 warp grid (warp tile 32x32), 3-stage K=64 ring
// ------------------------------------------------------------------
__global__ void __launch_bounds__(128, 4) lse_kernel() {
    extern __shared__ char dyn[];
    __shared__ int s_item;
    __shared__ float s_m1[64], s_s1[64];

    const int tid = threadIdx.x;
    const int warp = tid >> 5;
    const int lane = tid & 31;
    const int wm = warp >> 1;          // 0..1: M half
    const int wn = warp & 1;           // 0..1: N half
    const uint32_t ring = smem_u32(dyn);

    const int S = g_S;
    const int total = g_total;
    const int mt = g_mt;
    const int ntl = g_ntl;
    const int nitems = g_nitems;

    while (true) {
        if (tid == 0) s_item = atomicAdd(&g_work, 1);
        __syncthreads();                 // queue + guards smem reuse (ring & fold)
        const int item = s_item;
        if (item >= nitems) break;
        const int dir = item / (mt * ntl);
        const int rem = item % (mt * ntl);
        const int m = rem / ntl;
        const int n = rem % ntl;
        const int m0 = m * TILE;
        const int n0 = n * TILE;

        // cp.async: threads 0-63 load A rows, 64-127 load B rows (128B each)
        const __nv_bfloat16* srow;
        if (tid < 64) {
            srow = g_hidb + (size_t)dir * BT * Dn + (size_t)g_rowhid[min(m0 + tid, S - 1)] * Dn;
        } else {
            srow = g_bankb + (size_t)(n0 + tid - 64) * Dn;
        }
        const uint32_t cdst = ring + tid * STRIDE;   // row tid within stage

        auto issue = [&](int kc) {
            const uint32_t st = cdst + (kc % STAGES) * STG_BYTES;
            const __nv_bfloat16* sp = srow + kc * KSTG;
#pragma unroll
            for (int i = 0; i < 8; i++) cp16(st + i * 16, sp + i * 8);
        };
        issue(0); cp_commit();
        issue(1); cp_commit();

        float acc[2][4][4];
#pragma unroll
        for (int t2 = 0; t2 < 2; t2++)
#pragma unroll
            for (int q = 0; q < 4; q++)
#pragma unroll
                for (int j = 0; j < 4; j++) acc[t2][q][j] = 0.f;

        for (int kc = 0; kc < NKC; kc++) {
            cp_wait1();
            __syncthreads();
            if (kc + 2 < NKC) issue(kc + 2);
            cp_commit();   // real or empty group keeps wait accounting uniform

            const uint32_t stg = ring + (kc % STAGES) * STG_BYTES;
#pragma unroll
            for (int ks = 0; ks < 2; ks++) {       // two k32 sub-chunks
                uint32_t a[2][2][4];               // [m16 tile][k16 half][4]
#pragma unroll
                for (int t2 = 0; t2 < 2; t2++) {
                    uint32_t aaddr = stg + (wm * 32 + t2 * 16 + (lane & 15)) * STRIDE
                                   + ks * 64 + ((lane >> 4) << 4);
                    ldsm_x4(a[t2][0], aaddr);
                    ldsm_x4(a[t2][1], aaddr + 32);
                }
#pragma unroll
                for (int q = 0; q < 4; q++) {
                    uint32_t baddr = stg + (64 + wn * 32 + q * 8 + (lane & 7)) * STRIDE
                                   + ks * 64 + (((lane >> 3) & 3) << 4);
                    uint32_t b0, b1, b2, b3;
                    ldsm_x4t(b0, b1, b2, b3, baddr);
#pragma unroll
                    for (int t2 = 0; t2 < 2; t2++) {
                        mma16816(acc[t2][q], a[t2][0], b0, b1);
                        mma16816(acc[t2][q], a[t2][1], b2, b3);
                    }
                }
            }
        }

        // ---- per-warp LSE fold: warp covers rows [m0+wm*32,+32), cols [n0+wn*32,+32) ----
        const int ncol0 = n0 + wn * 32;
        if (ncol0 + 32 > total) {
            int cb = ncol0 + (lane & 3) * 2;
#pragma unroll
            for (int q = 0; q < 4; q++) {
                int c = cb + q * 8;
#pragma unroll
                for (int t2 = 0; t2 < 2; t2++) {
                    if (c >= total)     { acc[t2][q][0] = -INFINITY; acc[t2][q][2] = -INFINITY; }
                    if (c + 1 >= total) { acc[t2][q][1] = -INFINITY; acc[t2][q][3] = -INFINITY; }
                }
            }
        }
        float wm_[2][2], ws_[2][2];   // [t2][row group 0/+8]
#pragma unroll
        for (int t2 = 0; t2 < 2; t2++) {
            float m0l = -INFINITY, m1l = -INFINITY;
#pragma unroll
            for (int q = 0; q < 4; q++) {
                m0l = fmaxf(m0l, fmaxf(acc[t2][q][0], acc[t2][q][1]));
                m1l = fmaxf(m1l, fmaxf(acc[t2][q][2], acc[t2][q][3]));
            }
            m0l = fmaxf(m0l, __shfl_xor_sync(0xffffffffu, m0l, 1));
            m0l = fmaxf(m0l, __shfl_xor_sync(0xffffffffu, m0l, 2));
            m1l = fmaxf(m1l, __shfl_xor_sync(0xffffffffu, m1l, 1));
            m1l = fmaxf(m1l, __shfl_xor_sync(0xffffffffu, m1l, 2));
            m0l = fmaxf(m0l, -1e30f);
            m1l = fmaxf(m1l, -1e30f);
            float s0 = 0.f, s1 = 0.f;
#pragma unroll
            for (int q = 0; q < 4; q++) {
                s0 += __expf(acc[t2][q][0] - m0l) + __expf(acc[t2][q][1] - m0l);
                s1 += __expf(acc[t2][q][2] - m1l) + __expf(acc[t2][q][3] - m1l);
            }
            s0 += __shfl_xor_sync(0xffffffffu, s0, 1);
            s0 += __shfl_xor_sync(0xffffffffu, s0, 2);
            s1 += __shfl_xor_sync(0xffffffffu, s1, 1);
            s1 += __shfl_xor_sync(0xffffffffu, s1, 2);
            wm_[t2][0] = m0l; ws_[t2][0] = s0;
            wm_[t2][1] = m1l; ws_[t2][1] = s1;
        }
        // ---- merge the two n-halves (wn=0/1 share rows) via smem ----
        if (wn == 1 && (lane & 3) == 0) {
#pragma unroll
            for (int t2 = 0; t2 < 2; t2++)
#pragma unroll
                for (int g = 0; g < 2; g++) {
                    int lr = wm * 32 + t2 * 16 + (lane >> 2) + g * 8;
                    s_m1[lr] = wm_[t2][g]; s_s1[lr] = ws_[t2][g];
                }
        }
        __syncthreads();
        if (wn == 0 && (lane & 3) == 0) {
            const int base = (dir * NTL_MAX + n) * BT;
#pragma unroll
            for (int t2 = 0; t2 < 2; t2++)
#pragma unroll
                for (int g = 0; g < 2; g++) {
                    int lr = wm * 32 + t2 * 16 + (lane >> 2) + g * 8;
                    float ma = wm_[t2][g], sa = ws_[t2][g];
                    float mb = s_m1[lr],  sb = s_s1[lr];
                    float M = fmaxf(ma, mb);
                    float s = 0.f;
                    if (sa > 0.f) s += sa * __expf(ma - M);
                    if (sb > 0.f) s += sb * __expf(mb - M);
                    g_pm[base + m0 + lr] = M;
                    g_ps[base + m0 + lr] = s;
                }
        }
    }
}

// ------------------------------------------------------------------
// 5) combine N-tile partials into lse per row
// ------------------------------------------------------------------
__global__ void combine_kernel() {
    int idx = blockIdx.x * blockDim.x + threadIdx.x;
    if (idx >= 2 * BT) return;
    int dir = idx / BT, r = idx % BT;
    if (r >= g_S) return;
    int ntl = g_ntl;
    float M = -INFINITY;
    for (int c = 0; c < ntl; c++)
        M = fmaxf(M, g_pm[(dir * NTL_MAX + c) * BT + r]);
    float s = 0.f;
    for (int c = 0; c < ntl; c++) {
        float mm = g_pm[(dir * NTL_MAX + c) * BT + r];
        float ss = g_ps[(dir * NTL_MAX + c) * BT + r];
        if (ss > 0.f) s += ss * __expf(mm - M);
    }
    g_lse[dir * BT + r] = M + logf(s);
}

// ------------------------------------------------------------------
// 6) final reduction -> out[0]=fw_loss, out[1]=bw_loss
// ------------------------------------------------------------------
__global__ void reduce_kernel(float* __restrict__ out) {
    __shared__ double sh[256][2];
    int tid = threadIdx.x;
    int S = g_S;
    double a0 = 0.0, a1 = 0.0;
    for (int r = tid; r < S; r += 256) {
        double w = (double)g_invL[g_rowbatch[r]];
        a0 += (double)(g_lse[r]      - g_diag[r])      * w;
        a1 += (double)(g_lse[BT + r] - g_diag[BT + r]) * w;
    }
    sh[tid][0] = a0; sh[tid][1] = a1;
    __syncthreads();
    for (int o = 128; o >= 1; o >>= 1) {
        if (tid < o) { sh[tid][0] += sh[tid + o][0]; sh[tid][1] += sh[tid + o][1]; }
        __syncthreads();
    }
    if (tid == 0) {
        out[0] = (float)(sh[0][0] / (double)Bn);
        out[1] = (float)(sh[0][1] / (double)Bn);
    }
}

// ------------------------------------------------------------------
extern "C" void kernel_launch(void* const* d_in, const int* in_sizes, int n_in,
                              void* d_out, int out_size) {
    const float* feats    = (const float*)d_in[0];
    const float* hidden   = (const float*)d_in[1];
    const int*   seq_lens = (const int*)d_in[2];
    float* out = (float*)d_out;

    cudaFuncSetAttribute(lse_kernel, cudaFuncAttributeMaxDynamicSharedMemorySize, DYN_BYTES);

    setup_kernel<<<1, 256>>>(seq_lens);
    cvt_kernel<<<BT + TOTPAD, 256>>>(hidden, feats);
    diag_kernel<<<dim3(BT / 8, 2), 256>>>(hidden, feats);
    lse_kernel<<<NWORKERS, 128, DYN_BYTES>>>();
    combine_kernel<<<(2 * BT + 255) / 256, 256>>>();
    reduce_kernel<<<1, 256>>>(out);
    (void)in_sizes; (void)n_in; (void)out_size;
}

// round 8
// speedup vs baseline: 1.5187x; 1.5187x over previous
#include <cuda_runtime.h>
#include <cuda_bf16.h>
#include <math.h>
#include <stdint.h>

// ----- problem constants (B=16, T=512, D=512) -----
constexpr int Bn = 16;
constexpr int Tn = 512;
constexpr int Dn = 512;
constexpr int BT = Bn * Tn;            // 8192
constexpr int TOTPAD = 8320;           // 65*128 max bank rows (padded)
constexpr int NT_MAX = 65;             // worst-case N tiles
constexpr int KC = 32;                 // K per chunk
constexpr int NKCH = Dn / KC;          // 16
constexpr int STRIDE_B = 80;           // bytes per smem row (32 bf16 + pad) - conflict-free
constexpr int OP_BYTES = 128 * STRIDE_B;        // 10240 per operand per stage
constexpr int STG_BYTES = 2 * OP_BYTES;         // 20480 (A then B)
constexpr int STAGES = 5;
constexpr int DYN_BYTES = STAGES * STG_BYTES;   // 102400
constexpr int NWORKERS = 296;
constexpr int DROWS = 64;              // rows per diag work item

// ----- device scratch (no allocations allowed) -----
__device__ __nv_bfloat16 g_hidb[2 * BT * Dn];    // [dir][row][512]
__device__ __nv_bfloat16 g_bankb[TOTPAD * Dn];   // zero-padded bank, bf16
__device__ int   g_src[TOTPAD];
__device__ int   g_rowhid[BT];
__device__ int   g_rowbatch[BT];
__device__ int   g_L[Bn];
__device__ float g_invL[Bn];
__device__ int   g_S, g_total, g_mt, g_ntl, g_nitems, g_ndiag, g_work;
__device__ float g_pm[2 * NT_MAX * BT];
__device__ float g_ps[2 * NT_MAX * BT];
__device__ float g_diag[2 * BT];
__device__ double g_acc[2];

// ----- helpers -----
__device__ __forceinline__ uint32_t smem_u32(const void* p) {
    uint32_t a;
    asm("{ .reg .u64 t; cvta.to.shared.u64 t, %1; cvt.u32.u64 %0, t; }" : "=r"(a) : "l"(p));
    return a;
}
__device__ __forceinline__ void cp16(uint32_t dst, const void* src) {
    asm volatile("cp.async.cg.shared.global [%0], [%1], 16;" :: "r"(dst), "l"(src) : "memory");
}
__device__ __forceinline__ void cp_commit() {
    asm volatile("cp.async.commit_group;" ::: "memory");
}
__device__ __forceinline__ void cp_wait3() {
    asm volatile("cp.async.wait_group 3;" ::: "memory");
}
__device__ __forceinline__ void ldsm_x4(uint32_t& r0, uint32_t& r1, uint32_t& r2, uint32_t& r3, uint32_t a) {
    asm volatile("ldmatrix.sync.aligned.m8n8.x4.shared.b16 {%0,%1,%2,%3}, [%4];"
                 : "=r"(r0), "=r"(r1), "=r"(r2), "=r"(r3) : "r"(a));
}
__device__ __forceinline__ void ldsm_x4t(uint32_t& r0, uint32_t& r1, uint32_t& r2, uint32_t& r3, uint32_t a) {
    asm volatile("ldmatrix.sync.aligned.m8n8.x4.trans.shared.b16 {%0,%1,%2,%3}, [%4];"
                 : "=r"(r0), "=r"(r1), "=r"(r2), "=r"(r3) : "r"(a));
}
__device__ __forceinline__ void mma16816(float* c, const uint32_t* a, uint32_t b0, uint32_t b1) {
    asm volatile("mma.sync.aligned.m16n8k16.row.col.f32.bf16.bf16.f32 "
                 "{%0,%1,%2,%3}, {%4,%5,%6,%7}, {%8,%9}, {%0,%1,%2,%3};"
                 : "+f"(c[0]), "+f"(c[1]), "+f"(c[2]), "+f"(c[3])
                 : "r"(a[0]), "r"(a[1]), "r"(a[2]), "r"(a[3]), "r"(b0), "r"(b1));
}
__device__ __forceinline__ uint32_t f2bf2(float lo, float hi) {
    uint32_t r;
    asm("cvt.rn.bf16x2.f32 %0, %1, %2;" : "=r"(r) : "f"(hi), "f"(lo));
    return r;
}

// ------------------------------------------------------------------
// 1) layout setup (single block)
// ------------------------------------------------------------------
__global__ void setup_kernel(const int* __restrict__ seq_lens) {
    __shared__ int sL[Bn], sCum[Bn + 1], sStart[Bn];
    int tid = threadIdx.x;
    if (tid == 0) {
        int c = 0;
        for (int i = 0; i < Bn; i++) {
            sL[i] = seq_lens[i];
            sCum[i] = c;
            sStart[i] = 2 * i + c;
            c += sL[i];
        }
        sCum[Bn] = c;
        g_S = c;
        g_total = c + 2 * Bn;
        g_mt = (c + 127) / 128;
        g_ntl = (g_total + 127) / 128;
        g_ndiag = (c + DROWS - 1) / DROWS;
        g_nitems = g_ndiag + g_mt * g_ntl * 2;
        g_work = 0;
        g_acc[0] = 0.0; g_acc[1] = 0.0;
    }
    __syncthreads();
    int S = sCum[Bn];
    int total = S + 2 * Bn;
    if (tid < Bn) { g_invL[tid] = 1.0f / (float)sL[tid]; g_L[tid] = sL[tid]; }

    for (int r = tid; r < TOTPAD; r += blockDim.x) {
        int src = -1;
        if (r < total) {
            for (int i = 0; i < Bn; i++) {
                int s0 = sStart[i];
                if (r >= s0 && r < s0 + sL[i] + 2) {
                    if (r > s0 && r < s0 + sL[i] + 1) src = i * Tn + (r - s0 - 1);
                    break;
                }
            }
        }
        g_src[r] = src;
    }
    for (int r = tid; r < BT; r += blockDim.x) {
        if (r < S) {
            int b = 0;
            for (int i = 0; i < Bn; i++)
                if (r >= sCum[i] && r < sCum[i + 1]) { b = i; break; }
            int t = r - sCum[b];
            g_rowhid[r] = b * Tn + t;
            g_rowbatch[r] = b;
        } else {
            g_rowhid[r] = 0; g_rowbatch[r] = 0;
        }
    }
}

// ------------------------------------------------------------------
// 2) fused conversion: hidden -> per-dir bf16, feats -> bf16 bank
// ------------------------------------------------------------------
__global__ void cvt_kernel(const float* __restrict__ hidden,
                           const float* __restrict__ feats) {
    int blk = blockIdx.x;
    int tid = threadIdx.x;
    if (blk < BT) {
        float4 v = reinterpret_cast<const float4*>(hidden)[blk * 256 + tid];
        int dir = tid >= 128;
        int col = tid * 4 - dir * 512;
        uint2 o = make_uint2(f2bf2(v.x, v.y), f2bf2(v.z, v.w));
        *reinterpret_cast<uint2*>(&g_hidb[((size_t)dir * BT + blk) * Dn + col]) = o;
    } else if (tid < 128) {
        int row = blk - BT;
        int src = g_src[row];
        float4 v = make_float4(0.f, 0.f, 0.f, 0.f);
        if (src >= 0) v = reinterpret_cast<const float4*>(feats)[src * 128 + tid];
        uint2 o = make_uint2(f2bf2(v.x, v.y), f2bf2(v.z, v.w));
        *reinterpret_cast<uint2*>(&g_bankb[(size_t)row * Dn + tid * 4]) = o;
    }
}

// ------------------------------------------------------------------
// 3) persistent worker: diag items first, then GEMM+LSE tiles
//    grid 296 x 256 threads
// ------------------------------------------------------------------
__global__ void __launch_bounds__(256, 2) lse_kernel(const float* __restrict__ hidden,
                                                     const float* __restrict__ feats) {
    extern __shared__ char dyn[];
    __shared__ int s_item;

    const int tid = threadIdx.x;
    const int warp = tid >> 5;
    const int lane = tid & 31;
    const uint32_t ring = smem_u32(dyn);

    const int S = g_S;
    const int total = g_total;
    const int mt = g_mt;
    const int ntl = g_ntl;
    const int ndiag = g_ndiag;
    const int nitems = g_nitems;

    // cp.async geometry: rows ra=tid>>2 and ra+64, seg tid&3
    const int ra = tid >> 2;
    const int seg = tid & 3;
    const uint32_t dA0 = ra * STRIDE_B + seg * 16;
    const uint32_t dA1 = dA0 + 64 * STRIDE_B;
    const uint32_t dB0 = OP_BYTES + dA0;
    const uint32_t dB1 = OP_BYTES + dA1;

    while (true) {
        if (tid == 0) s_item = atomicAdd(&g_work, 1);
        __syncthreads();                 // also guards smem ring reuse
        const int item = s_item;
        if (item >= nitems) break;

        if (item < ndiag) {
            // ---------------- diag item: exact fp32 dot products, 64 rows, both dirs ----------------
            const int r0 = item * DROWS;
#pragma unroll
            for (int g = 0; g < 8; g++) {
                int r = r0 + warp * 8 + g;
                if (r >= S) break;
                int hrow = g_rowhid[r];
                int b = hrow >> 9, t = hrow & 511;
#pragma unroll
                for (int dir = 0; dir < 2; dir++) {
                    bool ok = dir == 0 ? (t + 1 < g_L[b]) : (t > 0);
                    float sum = 0.f;
                    if (ok) {
                        int frow = hrow + (dir == 0 ? 1 : -1);
                        const float4* h = reinterpret_cast<const float4*>(hidden + (size_t)hrow * 1024 + dir * Dn);
                        const float4* x = reinterpret_cast<const float4*>(feats + (size_t)frow * Dn);
#pragma unroll
                        for (int j = 0; j < 4; j++) {
                            float4 a = h[lane + j * 32];
                            float4 c = x[lane + j * 32];
                            sum += a.x * c.x + a.y * c.y + a.z * c.z + a.w * c.w;
                        }
#pragma unroll
                        for (int o = 16; o >= 1; o >>= 1) sum += __shfl_xor_sync(0xffffffffu, sum, o);
                    }
                    if (lane == 0) g_diag[dir * BT + r] = sum;
                }
            }
            continue;
        }

        const int gi = item - ndiag;
        const int dir = gi / (mt * ntl);
        const int rem = gi % (mt * ntl);
        const int m = rem / ntl;
        const int n = rem % ntl;
        const int m0 = m * 128;
        const int n0 = n * 128;

        // source row pointers for this thread's cp.async rows
        const __nv_bfloat16* hb = g_hidb + (size_t)dir * BT * Dn;
        const __nv_bfloat16* a_src0 = hb + (size_t)g_rowhid[min(m0 + ra, S - 1)] * Dn + seg * 8;
        const __nv_bfloat16* a_src1 = hb + (size_t)g_rowhid[min(m0 + ra + 64, S - 1)] * Dn + seg * 8;
        const __nv_bfloat16* b_src0 = g_bankb + (size_t)(n0 + ra) * Dn + seg * 8;
        const __nv_bfloat16* b_src1 = b_src0 + (size_t)64 * Dn;

        auto issue = [&](int kc, int stg) {
            const uint32_t st = ring + stg * STG_BYTES;
            const int ko = kc * KC;
            cp16(st + dA0, a_src0 + ko);
            cp16(st + dA1, a_src1 + ko);
            cp16(st + dB0, b_src0 + ko);
            cp16(st + dB1, b_src1 + ko);
        };
#pragma unroll
        for (int p = 0; p < 4; p++) { issue(p, p); cp_commit(); }

        float acc[16][4];
#pragma unroll
        for (int q = 0; q < 16; q++)
#pragma unroll
            for (int j = 0; j < 4; j++) acc[q][j] = 0.f;

        for (int kc = 0; kc < NKCH; kc++) {
            cp_wait3();
            __syncthreads();
            int nx = kc + 4;
            if (nx < NKCH) issue(nx, nx % STAGES);
            cp_commit();   // real or empty group keeps wait_group 3 invariant

            const uint32_t stA = ring + (kc % STAGES) * STG_BYTES;
            const uint32_t stB = stA + OP_BYTES;
            uint32_t a[2][4];
            {
                uint32_t aaddr = stA + (warp * 16 + (lane & 15)) * STRIDE_B + ((lane >> 4) << 4);
                ldsm_x4(a[0][0], a[0][1], a[0][2], a[0][3], aaddr);
                ldsm_x4(a[1][0], a[1][1], a[1][2], a[1][3], aaddr + 32);
            }
#pragma unroll
            for (int q = 0; q < 16; q++) {
                uint32_t baddr = stB + (q * 8 + (lane & 7)) * STRIDE_B + (((lane >> 3) & 3) << 4);
                uint32_t b0, b1, b2, b3;
                ldsm_x4t(b0, b1, b2, b3, baddr);
                mma16816(acc[q], a[0], b0, b1);
                mma16816(acc[q], a[1], b2, b3);
            }
        }

        // ---- per-tile LSE fold (rows lane>>2 and +8 of this warp's 16) ----
        if (n0 + 128 > total) {
            int cb = n0 + (lane & 3) * 2;
#pragma unroll
            for (int q = 0; q < 16; q++) {
                int c = cb + q * 8;
                if (c >= total)     { acc[q][0] = -INFINITY; acc[q][2] = -INFINITY; }
                if (c + 1 >= total) { acc[q][1] = -INFINITY; acc[q][3] = -INFINITY; }
            }
        }
        float m0l = -INFINITY, m1l = -INFINITY;
#pragma unroll
        for (int q = 0; q < 16; q++) {
            m0l = fmaxf(m0l, fmaxf(acc[q][0], acc[q][1]));
            m1l = fmaxf(m1l, fmaxf(acc[q][2], acc[q][3]));
        }
        m0l = fmaxf(m0l, __shfl_xor_sync(0xffffffffu, m0l, 1));
        m0l = fmaxf(m0l, __shfl_xor_sync(0xffffffffu, m0l, 2));
        m1l = fmaxf(m1l, __shfl_xor_sync(0xffffffffu, m1l, 1));
        m1l = fmaxf(m1l, __shfl_xor_sync(0xffffffffu, m1l, 2));
        m0l = fmaxf(m0l, -1e30f);
        m1l = fmaxf(m1l, -1e30f);
        float s0 = 0.f, s1 = 0.f;
#pragma unroll
        for (int q = 0; q < 16; q++) {
            s0 += __expf(acc[q][0] - m0l) + __expf(acc[q][1] - m0l);
            s1 += __expf(acc[q][2] - m1l) + __expf(acc[q][3] - m1l);
        }
        s0 += __shfl_xor_sync(0xffffffffu, s0, 1);
        s0 += __shfl_xor_sync(0xffffffffu, s0, 2);
        s1 += __shfl_xor_sync(0xffffffffu, s1, 1);
        s1 += __shfl_xor_sync(0xffffffffu, s1, 2);

        if ((lane & 3) == 0) {
            int r0 = m0 + warp * 16 + (lane >> 2);
            int base = (dir * NT_MAX + n) * BT;
            g_pm[base + r0] = m0l;     g_ps[base + r0] = s0;
            g_pm[base + r0 + 8] = m1l; g_ps[base + r0 + 8] = s1;
        }
    }
}

// ------------------------------------------------------------------
// 4) combine N-tile partials into lse per row, fold loss partials
// ------------------------------------------------------------------
__global__ void combine_kernel() {
    __shared__ double sh[256][2];
    int tid = threadIdx.x;
    int idx = blockIdx.x * blockDim.x + tid;
    int S = g_S, ntl = g_ntl;
    double a0 = 0.0, a1 = 0.0;
    int r = idx;
    if (r < S) {
        double w = (double)g_invL[g_rowbatch[r]];
#pragma unroll
        for (int dir = 0; dir < 2; dir++) {
            float M = -INFINITY;
            for (int c = 0; c < ntl; c++)
                M = fmaxf(M, g_pm[(dir * NT_MAX + c) * BT + r]);
            float s = 0.f;
            for (int c = 0; c < ntl; c++) {
                float mm = g_pm[(dir * NT_MAX + c) * BT + r];
                float ss = g_ps[(dir * NT_MAX + c) * BT + r];
                if (ss > 0.f) s += ss * __expf(mm - M);
            }
            float lse = M + logf(s);
            double v = (double)(lse - g_diag[dir * BT + r]) * w;
            if (dir == 0) a0 = v; else a1 = v;
        }
    }
    sh[tid][0] = a0; sh[tid][1] = a1;
    __syncthreads();
    for (int o = 128; o >= 1; o >>= 1) {
        if (tid < o) { sh[tid][0] += sh[tid + o][0]; sh[tid][1] += sh[tid + o][1]; }
        __syncthreads();
    }
    if (tid == 0) {
        atomicAdd(&g_acc[0], sh[0][0]);
        atomicAdd(&g_acc[1], sh[0][1]);
    }
}

// ------------------------------------------------------------------
// 5) finalize -> out[0]=fw_loss, out[1]=bw_loss
// ------------------------------------------------------------------
__global__ void final_kernel(float* __restrict__ out) {
    if (threadIdx.x == 0) {
        out[0] = (float)(g_acc[0] / (double)Bn);
        out[1] = (float)(g_acc[1] / (double)Bn);
    }
}

// ------------------------------------------------------------------
extern "C" void kernel_launch(void* const* d_in, const int* in_sizes, int n_in,
                              void* d_out, int out_size) {
    const float* feats    = (const float*)d_in[0];
    const float* hidden   = (const float*)d_in[1];
    const int*   seq_lens = (const int*)d_in[2];
    float* out = (float*)d_out;

    cudaFuncSetAttribute(lse_kernel, cudaFuncAttributeMaxDynamicSharedMemorySize, DYN_BYTES);

    setup_kernel<<<1, 256>>>(seq_lens);
    cvt_kernel<<<BT + TOTPAD, 256>>>(hidden, feats);
    lse_kernel<<<NWORKERS, 256, DYN_BYTES>>>(hidden, feats);
    combine_kernel<<<BT / 256, 256>>>();
    final_kernel<<<1, 32>>>(out);
    (void)in_sizes; (void)n_in; (void)out_size;
}

// round 11
// speedup vs baseline: 1.5694x; 1.0334x over previous
#include <cuda_runtime.h>
#include <cuda_bf16.h>
#include <math.h>
#include <stdint.h>

// ----- problem constants (B=16, T=512, D=512) -----
constexpr int Bn = 16;
constexpr int Tn = 512;
constexpr int Dn = 512;
constexpr int BT = Bn * Tn;            // 8192
constexpr int TOTPAD = 8320;           // 65*128 max bank rows (padded)
constexpr int NTP = 68;                // padded per-row tile stride (16B aligned)
constexpr int KC = 32;                 // K per chunk
constexpr int NKCH = Dn / KC;          // 16
constexpr int STRIDE_B = 80;           // bytes per smem row (32 bf16 + pad) - conflict-free
constexpr int OP_BYTES = 128 * STRIDE_B;        // 10240 per operand per stage
constexpr int STG_BYTES = 2 * OP_BYTES;         // 20480 (A then B)
constexpr int STAGES = 5;
constexpr int DYN_BYTES = STAGES * STG_BYTES;   // 102400
constexpr int NWORKERS = 296;
constexpr int DROWS = 64;              // rows per diag work item

// ----- device scratch (no allocations allowed) -----
__device__ __nv_bfloat16 g_hidb[2 * BT * Dn];    // [dir][row][512]
__device__ __nv_bfloat16 g_bankb[TOTPAD * Dn];   // zero-padded bank, bf16
__device__ int   g_src[TOTPAD];
__device__ int   g_rowhid[BT];
__device__ int   g_rowbatch[BT];
__device__ int   g_L[Bn];
__device__ float g_invL[Bn];
__device__ int   g_S, g_total, g_mt, g_ntl, g_nitems, g_ndiag, g_work;
__device__ __align__(16) float g_pm[2 * BT * NTP];   // [dir*BT + row][tile]
__device__ __align__(16) float g_ps[2 * BT * NTP];
__device__ float g_diag[2 * BT];
__device__ double g_acc[2];

// ----- helpers -----
__device__ __forceinline__ uint32_t smem_u32(const void* p) {
    uint32_t a;
    asm("{ .reg .u64 t; cvta.to.shared.u64 t, %1; cvt.u32.u64 %0, t; }" : "=r"(a) : "l"(p));
    return a;
}
__device__ __forceinline__ void cp16(uint32_t dst, const void* src) {
    asm volatile("cp.async.cg.shared.global [%0], [%1], 16;" :: "r"(dst), "l"(src) : "memory");
}
__device__ __forceinline__ void cp_commit() {
    asm volatile("cp.async.commit_group;" ::: "memory");
}
__device__ __forceinline__ void cp_wait3() {
    asm volatile("cp.async.wait_group 3;" ::: "memory");
}
__device__ __forceinline__ void ldsm_x4(uint32_t& r0, uint32_t& r1, uint32_t& r2, uint32_t& r3, uint32_t a) {
    asm volatile("ldmatrix.sync.aligned.m8n8.x4.shared.b16 {%0,%1,%2,%3}, [%4];"
                 : "=r"(r0), "=r"(r1), "=r"(r2), "=r"(r3) : "r"(a));
}
__device__ __forceinline__ void ldsm_x4t(uint32_t& r0, uint32_t& r1, uint32_t& r2, uint32_t& r3, uint32_t a) {
    asm volatile("ldmatrix.sync.aligned.m8n8.x4.trans.shared.b16 {%0,%1,%2,%3}, [%4];"
                 : "=r"(r0), "=r"(r1), "=r"(r2), "=r"(r3) : "r"(a));
}
__device__ __forceinline__ void mma16816(float* c, const uint32_t* a, uint32_t b0, uint32_t b1) {
    asm volatile("mma.sync.aligned.m16n8k16.row.col.f32.bf16.bf16.f32 "
                 "{%0,%1,%2,%3}, {%4,%5,%6,%7}, {%8,%9}, {%0,%1,%2,%3};"
                 : "+f"(c[0]), "+f"(c[1]), "+f"(c[2]), "+f"(c[3])
                 : "r"(a[0]), "r"(a[1]), "r"(a[2]), "r"(a[3]), "r"(b0), "r"(b1));
}
__device__ __forceinline__ uint32_t f2bf2(float lo, float hi) {
    uint32_t r;
    asm("cvt.rn.bf16x2.f32 %0, %1, %2;" : "=r"(r) : "f"(hi), "f"(lo));
    return r;
}

// ------------------------------------------------------------------
// 1) layout setup (single block)
// ------------------------------------------------------------------
__global__ void setup_kernel(const int* __restrict__ seq_lens) {
    __shared__ int sL[Bn], sCum[Bn + 1], sStart[Bn];
    int tid = threadIdx.x;
    if (tid == 0) {
        int c = 0;
        for (int i = 0; i < Bn; i++) {
            sL[i] = seq_lens[i];
            sCum[i] = c;
            sStart[i] = 2 * i + c;
            c += sL[i];
        }
        sCum[Bn] = c;
        g_S = c;
        g_total = c + 2 * Bn;
        g_mt = (c + 127) / 128;
        g_ntl = (g_total + 127) / 128;
        g_ndiag = (c + DROWS - 1) / DROWS;
        g_nitems = g_ndiag + g_mt * g_ntl * 2;
        g_work = 0;
        g_acc[0] = 0.0; g_acc[1] = 0.0;
    }
    __syncthreads();
    int S = sCum[Bn];
    int total = S + 2 * Bn;
    if (tid < Bn) { g_invL[tid] = 1.0f / (float)sL[tid]; g_L[tid] = sL[tid]; }

    for (int r = tid; r < TOTPAD; r += blockDim.x) {
        int src = -1;
        if (r < total) {
            for (int i = 0; i < Bn; i++) {
                int s0 = sStart[i];
                if (r >= s0 && r < s0 + sL[i] + 2) {
                    if (r > s0 && r < s0 + sL[i] + 1) src = i * Tn + (r - s0 - 1);
                    break;
                }
            }
        }
        g_src[r] = src;
    }
    for (int r = tid; r < BT; r += blockDim.x) {
        if (r < S) {
            int b = 0;
            for (int i = 0; i < Bn; i++)
                if (r >= sCum[i] && r < sCum[i + 1]) { b = i; break; }
            int t = r - sCum[b];
            g_rowhid[r] = b * Tn + t;
            g_rowbatch[r] = b;
        } else {
            g_rowhid[r] = 0; g_rowbatch[r] = 0;
        }
    }
}

// ------------------------------------------------------------------
// 2) fused conversion: hidden -> per-dir bf16, feats -> bf16 bank
// ------------------------------------------------------------------
__global__ void cvt_kernel(const float* __restrict__ hidden,
                           const float* __restrict__ feats) {
    int blk = blockIdx.x;
    int tid = threadIdx.x;
    if (blk < BT) {
        float4 v = reinterpret_cast<const float4*>(hidden)[blk * 256 + tid];
        int dir = tid >= 128;
        int col = tid * 4 - dir * 512;
        uint2 o = make_uint2(f2bf2(v.x, v.y), f2bf2(v.z, v.w));
        *reinterpret_cast<uint2*>(&g_hidb[((size_t)dir * BT + blk) * Dn + col]) = o;
    } else if (tid < 128) {
        int row = blk - BT;
        int src = g_src[row];
        float4 v = make_float4(0.f, 0.f, 0.f, 0.f);
        if (src >= 0) v = reinterpret_cast<const float4*>(feats)[src * 128 + tid];
        uint2 o = make_uint2(f2bf2(v.x, v.y), f2bf2(v.z, v.w));
        *reinterpret_cast<uint2*>(&g_bankb[(size_t)row * Dn + tid * 4]) = o;
    }
}

// ------------------------------------------------------------------
// 3) persistent worker: diag items first, then GEMM+LSE tiles
//    grid 296 x 256 threads
// ------------------------------------------------------------------
__global__ void __launch_bounds__(256, 2) lse_kernel(const float* __restrict__ hidden,
                                                     const float* __restrict__ feats) {
    extern __shared__ char dyn[];
    __shared__ int s_item;

    const int tid = threadIdx.x;
    const int warp = tid >> 5;
    const int lane = tid & 31;
    const uint32_t ring = smem_u32(dyn);

    const int S = g_S;
    const int total = g_total;
    const int mt = g_mt;
    const int ntl = g_ntl;
    const int ndiag = g_ndiag;
    const int nitems = g_nitems;

    // cp.async geometry: rows ra=tid>>2 and ra+64, seg tid&3
    const int ra = tid >> 2;
    const int seg = tid & 3;
    const uint32_t dA0 = ra * STRIDE_B + seg * 16;
    const uint32_t dA1 = dA0 + 64 * STRIDE_B;
    const uint32_t dB0 = OP_BYTES + dA0;
    const uint32_t dB1 = OP_BYTES + dA1;

    while (true) {
        if (tid == 0) s_item = atomicAdd(&g_work, 1);
        __syncthreads();                 // also guards smem ring reuse
        const int item = s_item;
        if (item >= nitems) break;

        if (item < ndiag) {
            // ---------------- diag item: exact fp32 dot products, 64 rows, both dirs ----------------
            const int r0 = item * DROWS;
#pragma unroll
            for (int g = 0; g < 8; g++) {
                int r = r0 + warp * 8 + g;
                if (r >= S) break;
                int hrow = g_rowhid[r];
                int b = hrow >> 9, t = hrow & 511;
#pragma unroll
                for (int dir = 0; dir < 2; dir++) {
                    bool ok = dir == 0 ? (t + 1 < g_L[b]) : (t > 0);
                    float sum = 0.f;
                    if (ok) {
                        int frow = hrow + (dir == 0 ? 1 : -1);
                        const float4* h = reinterpret_cast<const float4*>(hidden + (size_t)hrow * 1024 + dir * Dn);
                        const float4* x = reinterpret_cast<const float4*>(feats + (size_t)frow * Dn);
#pragma unroll
                        for (int j = 0; j < 4; j++) {
                            float4 a = h[lane + j * 32];
                            float4 c = x[lane + j * 32];
                            sum += a.x * c.x + a.y * c.y + a.z * c.z + a.w * c.w;
                        }
#pragma unroll
                        for (int o = 16; o >= 1; o >>= 1) sum += __shfl_xor_sync(0xffffffffu, sum, o);
                    }
                    if (lane == 0) g_diag[dir * BT + r] = sum;
                }
            }
            continue;
        }

        const int gi = item - ndiag;
        const int dir = gi / (mt * ntl);
        const int rem = gi % (mt * ntl);
        const int m = rem / ntl;
        const int n = rem % ntl;
        const int m0 = m * 128;
        const int n0 = n * 128;

        // source row pointers for this thread's cp.async rows
        const __nv_bfloat16* hb = g_hidb + (size_t)dir * BT * Dn;
        const __nv_bfloat16* a_src0 = hb + (size_t)g_rowhid[min(m0 + ra, S - 1)] * Dn + seg * 8;
        const __nv_bfloat16* a_src1 = hb + (size_t)g_rowhid[min(m0 + ra + 64, S - 1)] * Dn + seg * 8;
        const __nv_bfloat16* b_src0 = g_bankb + (size_t)(n0 + ra) * Dn + seg * 8;
        const __nv_bfloat16* b_src1 = b_src0 + (size_t)64 * Dn;

        auto issue = [&](int kc, int stg) {
            const uint32_t st = ring + stg * STG_BYTES;
            const int ko = kc * KC;
            cp16(st + dA0, a_src0 + ko);
            cp16(st + dA1, a_src1 + ko);
            cp16(st + dB0, b_src0 + ko);
            cp16(st + dB1, b_src1 + ko);
        };
#pragma unroll
        for (int p = 0; p < 4; p++) { issue(p, p); cp_commit(); }

        float acc[16][4];
#pragma unroll
        for (int q = 0; q < 16; q++)
#pragma unroll
            for (int j = 0; j < 4; j++) acc[q][j] = 0.f;

        for (int kc = 0; kc < NKCH; kc++) {
            cp_wait3();
            __syncthreads();
            int nx = kc + 4;
            if (nx < NKCH) issue(nx, nx % STAGES);
            cp_commit();   // real or empty group keeps wait_group 3 invariant

            const uint32_t stA = ring + (kc % STAGES) * STG_BYTES;
            const uint32_t stB = stA + OP_BYTES;
            uint32_t a[2][4];
            {
                uint32_t aaddr = stA + (warp * 16 + (lane & 15)) * STRIDE_B + ((lane >> 4) << 4);
                ldsm_x4(a[0][0], a[0][1], a[0][2], a[0][3], aaddr);
                ldsm_x4(a[1][0], a[1][1], a[1][2], a[1][3], aaddr + 32);
            }
#pragma unroll
            for (int q = 0; q < 16; q++) {
                uint32_t baddr = stB + (q * 8 + (lane & 7)) * STRIDE_B + (((lane >> 3) & 3) << 4);
                uint32_t b0, b1, b2, b3;
                ldsm_x4t(b0, b1, b2, b3, baddr);
                mma16816(acc[q], a[0], b0, b1);
                mma16816(acc[q], a[1], b2, b3);
            }
        }

        // ---- per-tile LSE fold (rows lane>>2 and +8 of this warp's 16) ----
        if (n0 + 128 > total) {
            int cb = n0 + (lane & 3) * 2;
#pragma unroll
            for (int q = 0; q < 16; q++) {
                int c = cb + q * 8;
                if (c >= total)     { acc[q][0] = -INFINITY; acc[q][2] = -INFINITY; }
                if (c + 1 >= total) { acc[q][1] = -INFINITY; acc[q][3] = -INFINITY; }
            }
        }
        float m0l = -INFINITY, m1l = -INFINITY;
#pragma unroll
        for (int q = 0; q < 16; q++) {
            m0l = fmaxf(m0l, fmaxf(acc[q][0], acc[q][1]));
            m1l = fmaxf(m1l, fmaxf(acc[q][2], acc[q][3]));
        }
        m0l = fmaxf(m0l, __shfl_xor_sync(0xffffffffu, m0l, 1));
        m0l = fmaxf(m0l, __shfl_xor_sync(0xffffffffu, m0l, 2));
        m1l = fmaxf(m1l, __shfl_xor_sync(0xffffffffu, m1l, 1));
        m1l = fmaxf(m1l, __shfl_xor_sync(0xffffffffu, m1l, 2));
        m0l = fmaxf(m0l, -1e30f);
        m1l = fmaxf(m1l, -1e30f);
        float s0 = 0.f, s1 = 0.f;
#pragma unroll
        for (int q = 0; q < 16; q++) {
            s0 += __expf(acc[q][0] - m0l) + __expf(acc[q][1] - m0l);
            s1 += __expf(acc[q][2] - m1l) + __expf(acc[q][3] - m1l);
        }
        s0 += __shfl_xor_sync(0xffffffffu, s0, 1);
        s0 += __shfl_xor_sync(0xffffffffu, s0, 2);
        s1 += __shfl_xor_sync(0xffffffffu, s1, 1);
        s1 += __shfl_xor_sync(0xffffffffu, s1, 2);

        if ((lane & 3) == 0) {
            int r0 = m0 + warp * 16 + (lane >> 2);
            size_t base = (size_t)(dir * BT) * NTP + n;
            g_pm[base + (size_t)r0 * NTP] = m0l;       g_ps[base + (size_t)r0 * NTP] = s0;
            g_pm[base + (size_t)(r0 + 8) * NTP] = m1l; g_ps[base + (size_t)(r0 + 8) * NTP] = s1;
        }
    }
}

// ------------------------------------------------------------------
// 4) combine: per-(row,dir) lse from contiguous partials (float4),
//    fold loss partials into g_acc
// ------------------------------------------------------------------
__global__ void combine_kernel() {
    __shared__ double sh[256];
    int tid = threadIdx.x;
    int idx = blockIdx.x * blockDim.x + tid;   // over 2*BT (row, dir) pairs
    int S = g_S, ntl = g_ntl;
    int dir = idx >= BT;
    int r = idx - dir * BT;
    double a = 0.0;
    if (r < S) {
        const float* pm = g_pm + (size_t)(dir * BT + r) * NTP;
        const float* ps = g_ps + (size_t)(dir * BT + r) * NTP;
        const float4* pm4 = reinterpret_cast<const float4*>(pm);
        const float4* ps4 = reinterpret_cast<const float4*>(ps);
        int n4 = ntl >> 2;
        float M = -INFINITY;
        for (int c = 0; c < n4; c++) {
            float4 v = pm4[c];
            M = fmaxf(M, fmaxf(fmaxf(v.x, v.y), fmaxf(v.z, v.w)));
        }
        for (int c = n4 * 4; c < ntl; c++) M = fmaxf(M, pm[c]);
        float s = 0.f;
        for (int c = 0; c < n4; c++) {
            float4 vm = pm4[c];
            float4 vs = ps4[c];
            if (vs.x > 0.f) s += vs.x * __expf(vm.x - M);
            if (vs.y > 0.f) s += vs.y * __expf(vm.y - M);
            if (vs.z > 0.f) s += vs.z * __expf(vm.z - M);
            if (vs.w > 0.f) s += vs.w * __expf(vm.w - M);
        }
        for (int c = n4 * 4; c < ntl; c++) {
            if (ps[c] > 0.f) s += ps[c] * __expf(pm[c] - M);
        }
        float lse = M + logf(s);
        a = (double)(lse - g_diag[dir * BT + r]) * (double)g_invL[g_rowbatch[r]];
    }
    sh[tid] = a;
    __syncthreads();
    for (int o = 128; o >= 1; o >>= 1) {
        if (tid < o) sh[tid] += sh[tid + o];
        __syncthreads();
    }
    if (tid == 0) atomicAdd(&g_acc[dir], sh[0]);
}

// ------------------------------------------------------------------
// 5) finalize -> out[0]=fw_loss, out[1]=bw_loss
// ------------------------------------------------------------------
__global__ void final_kernel(float* __restrict__ out) {
    if (threadIdx.x == 0) {
        out[0] = (float)(g_acc[0] / (double)Bn);
        out[1] = (float)(g_acc[1] / (double)Bn);
    }
}

// ------------------------------------------------------------------
extern "C" void kernel_launch(void* const* d_in, const int* in_sizes, int n_in,
                              void* d_out, int out_size) {
    const float* feats    = (const float*)d_in[0];
    const float* hidden   = (const float*)d_in[1];
    const int*   seq_lens = (const int*)d_in[2];
    float* out = (float*)d_out;

    cudaFuncSetAttribute(lse_kernel, cudaFuncAttributeMaxDynamicSharedMemorySize, DYN_BYTES);

    setup_kernel<<<1, 256>>>(seq_lens);
    cvt_kernel<<<BT + TOTPAD, 256>>>(hidden, feats);
    lse_kernel<<<NWORKERS, 256, DYN_BYTES>>>(hidden, feats);
    combine_kernel<<<2 * BT / 256, 256>>>();
    final_kernel<<<1, 32>>>(out);
    (void)in_sizes; (void)n_in; (void)out_size;
}